// round 15
// baseline (speedup 1.0000x reference)
#include <cuda_runtime.h>
#include <cstdint>

#define NN 100000
#define NE 1600000
#define NF 128
#define HD 64

#define NB_N ((NN + 255) / 256)   // 391
#define NB_E ((NE + 255) / 256)   // 6250
#define GEMM1_BLOCKS 592

// ---------------- scratch (no allocs allowed) ----------------
__device__ __align__(16) float g_dinv[NN];
__device__ __align__(16) float g_t [NN * HD];    // buffer A
__device__ __align__(16) float g_t2[NN * HD];    // buffer B
__device__ __align__(16) float g_h [NN * HD];    // layer-3 output
__device__ __align__(16) int g_deg[NN];
__device__ __align__(16) int g_cursor[NN];
__device__ __align__(16) int g_rowstart[NN + 1];
__device__ __align__(16) int g_csr[NE];
__device__ float g_loss;
__device__ int   g_lsum;

// ---------------- 1: fused init (nodes) + count (edges) ----------------
__global__ void k_ic(const int* __restrict__ labels, const int* __restrict__ ei) {
    int bid = blockIdx.x;
    if (bid < NB_N) {
        int i = bid * 256 + threadIdx.x;
        if (i == 0) { g_loss = 0.f; g_lsum = 0; }
        int v = 0;
        if (i < NN) { g_deg[i] = 0; v = labels[i]; }
        #pragma unroll
        for (int off = 16; off; off >>= 1) v += __shfl_down_sync(0xffffffffu, v, off);
        if ((threadIdx.x & 31) == 0 && v) atomicAdd(&g_lsum, v);
    } else {
        int e = (bid - NB_N) * 256 + threadIdx.x;
        if (e < NE) {
            unsigned c = (unsigned)ei[NE + e];
            if (c < NN) atomicAdd(&g_deg[c], 1);
        }
    }
}

// ---------------- 2: 1-block scan -> rowstart, cursor, dinv ----------------
__global__ void k_scan() {
    const int T = 1024;
    const int CH = (NN + T - 1) / T;
    __shared__ int sh[T];
    int tid = threadIdx.x;
    int lo = tid * CH, hi = lo + CH; if (hi > NN) hi = NN;
    int s = 0;
    for (int i = lo; i < hi; i++) s += g_deg[i];
    sh[tid] = s;
    __syncthreads();
    for (int off = 1; off < T; off <<= 1) {
        int v = (tid >= off) ? sh[tid - off] : 0;
        __syncthreads();
        sh[tid] += v;
        __syncthreads();
    }
    int run = sh[tid] - s;
    for (int i = lo; i < hi; i++) {
        int d = g_deg[i];
        g_rowstart[i] = run;
        g_cursor[i]   = run;
        g_dinv[i]     = rsqrtf((float)(d + 1));
        run += d;
    }
    if (tid == T - 1) g_rowstart[NN] = run;
}

// ---------------- gemm1 body (R10-proven retile) ----------------
__device__ __forceinline__ void gemm1_body(const float* __restrict__ hin,
                                           const float* __restrict__ W,
                                           float* sW, float4 (*srow)[NF / 4],
                                           int bid, int nblocks) {
    int tid = threadIdx.x;
    for (int j = tid; j < NF * HD / 4; j += 256)
        ((float4*)sW)[j] = ((const float4*)W)[j];

    int c2 = tid & 31;
    int rt = tid >> 5;

    for (int rb = bid * 32; rb < NN; rb += nblocks * 32) {
        __syncthreads();
        for (int j = tid; j < 32 * (NF / 4); j += 256) {
            int r = j / (NF / 4), kk = j % (NF / 4);
            srow[r][kk] = ((const float4*)(hin + (size_t)(rb + r) * NF))[kk];
        }
        __syncthreads();

        float acc0[4], acc1[4];
        #pragma unroll
        for (int rr = 0; rr < 4; rr++) { acc0[rr] = 0.f; acc1[rr] = 0.f; }

        #pragma unroll
        for (int k4 = 0; k4 < NF / 4; k4++) {
            float2 wa = *(const float2*)&sW[(4 * k4 + 0) * HD + 2 * c2];
            float2 wb = *(const float2*)&sW[(4 * k4 + 1) * HD + 2 * c2];
            float2 wc = *(const float2*)&sW[(4 * k4 + 2) * HD + 2 * c2];
            float2 wd = *(const float2*)&sW[(4 * k4 + 3) * HD + 2 * c2];
            #pragma unroll
            for (int rr = 0; rr < 4; rr++) {
                float4 h = srow[rt * 4 + rr][k4];
                acc0[rr] = fmaf(h.x, wa.x, acc0[rr]);
                acc0[rr] = fmaf(h.y, wb.x, acc0[rr]);
                acc0[rr] = fmaf(h.z, wc.x, acc0[rr]);
                acc0[rr] = fmaf(h.w, wd.x, acc0[rr]);
                acc1[rr] = fmaf(h.x, wa.y, acc1[rr]);
                acc1[rr] = fmaf(h.y, wb.y, acc1[rr]);
                acc1[rr] = fmaf(h.z, wc.y, acc1[rr]);
                acc1[rr] = fmaf(h.w, wd.y, acc1[rr]);
            }
        }
        #pragma unroll
        for (int rr = 0; rr < 4; rr++) {
            int gr = rb + rt * 4 + rr;
            float d = g_dinv[gr];
            float2 o = make_float2(acc0[rr] * d, acc1[rr] * d);
            *(float2*)&g_t[(size_t)gr * HD + 2 * c2] = o;
        }
    }
}

// ---------------- 3: fused [gemm1 || fill] ----------------
__global__ void __launch_bounds__(256) k_gemmfill(const float* __restrict__ x,
                                                  const float* __restrict__ W1,
                                                  const int* __restrict__ ei) {
    __shared__ __align__(16) float  sW[NF * HD];        // 32KB
    __shared__ __align__(16) float4 srow[32][NF / 4];   // 16KB
    int bid = blockIdx.x;
    if (bid >= GEMM1_BLOCKS) {
        int e = (bid - GEMM1_BLOCKS) * 256 + threadIdx.x;
        if (e < NE) {
            unsigned src = (unsigned)ei[e];
            unsigned dst = (unsigned)ei[NE + e];
            if (src < NN && dst < NN) {
                int pos = atomicAdd(&g_cursor[dst], 1);
                g_csr[pos] = (int)src;
            }
        }
        return;
    }
    gemm1_body(x, W1, sW, srow, bid, GEMM1_BLOCKS);
}

// ---------------- gather core (R14-proven: unroll-4, two chains) ----------
__device__ __forceinline__ float4 gather_h(const float4* __restrict__ t4,
                                           int node, int part,
                                           const float* __restrict__ b) {
    int s = g_rowstart[node];
    int e = g_rowstart[node + 1];

    float4 a0 = t4[(size_t)node * 16 + part];   // self loop
    float4 a1 = make_float4(0.f, 0.f, 0.f, 0.f);
    int i = s;
    for (; i + 4 <= e; i += 4) {
        int s0 = g_csr[i],     s1 = g_csr[i + 1];
        int s2 = g_csr[i + 2], s3 = g_csr[i + 3];
        float4 v0 = t4[(size_t)s0 * 16 + part];
        float4 v1 = t4[(size_t)s1 * 16 + part];
        float4 v2 = t4[(size_t)s2 * 16 + part];
        float4 v3 = t4[(size_t)s3 * 16 + part];
        a0.x += v0.x; a0.y += v0.y; a0.z += v0.z; a0.w += v0.w;
        a1.x += v1.x; a1.y += v1.y; a1.z += v1.z; a1.w += v1.w;
        a0.x += v2.x; a0.y += v2.y; a0.z += v2.z; a0.w += v2.w;
        a1.x += v3.x; a1.y += v3.y; a1.z += v3.z; a1.w += v3.w;
    }
    for (; i < e; i++) {
        float4 v = t4[(size_t)g_csr[i] * 16 + part];
        a0.x += v.x; a0.y += v.y; a0.z += v.z; a0.w += v.w;
    }
    float4 acc = make_float4(a0.x + a1.x, a0.y + a1.y, a0.z + a1.z, a0.w + a1.w);

    float d = g_dinv[node];
    float4 bb = *(const float4*)&b[part * 4];
    float4 o;
    o.x = fmaxf(fmaf(d, acc.x, bb.x), 0.f);
    o.y = fmaxf(fmaf(d, acc.y, bb.y), 0.f);
    o.z = fmaxf(fmaf(d, acc.z, bb.z), 0.f);
    o.w = fmaxf(fmaf(d, acc.w, bb.w), 0.f);
    return o;
}

// ---------------- fused agg + next-layer GEMM ----------------
// SRCA: gather from g_t -> write g_t2, else g_t2 -> g_t.
// Epilogue per-element fmaf k-chain identical to the standalone gemm.
template <bool SRCA>
__global__ void __launch_bounds__(256) k_agg_gemm(const float* __restrict__ b,
                                                  const float* __restrict__ Wn) {
    __shared__ float sW[HD * HD];                 // 16KB
    __shared__ __align__(16) float shh[16][HD];   // 4KB
    int tid  = threadIdx.x;
    int nl   = tid >> 4;                          // node local 0..15
    int part = tid & 15;
    int node = blockIdx.x * 16 + nl;              // NN % 16 == 0

    // load W_next (overlaps the gather latency)
    for (int j = tid; j < HD * HD / 4; j += 256)
        ((float4*)sW)[j] = ((const float4*)Wn)[j];

    const float4* __restrict__ t4 = (const float4*)(SRCA ? g_t : g_t2);
    float* __restrict__ dst = SRCA ? g_t2 : g_t;

    float4 h = gather_h(t4, node, part, b);
    *(float4*)&shh[nl][part * 4] = h;
    __syncthreads();

    // epilogue: this thread computes cols [part*4, part*4+4) of its node
    float ac0 = 0.f, ac1 = 0.f, ac2 = 0.f, ac3 = 0.f;
    #pragma unroll
    for (int k4 = 0; k4 < HD / 4; k4++) {
        float4 hv = *(const float4*)&shh[nl][k4 * 4];   // broadcast in 16-group
        float4 w0 = *(const float4*)&sW[(4 * k4 + 0) * HD + part * 4];
        float4 w1 = *(const float4*)&sW[(4 * k4 + 1) * HD + part * 4];
        float4 w2 = *(const float4*)&sW[(4 * k4 + 2) * HD + part * 4];
        float4 w3 = *(const float4*)&sW[(4 * k4 + 3) * HD + part * 4];
        ac0 = fmaf(hv.x, w0.x, ac0); ac0 = fmaf(hv.y, w1.x, ac0);
        ac0 = fmaf(hv.z, w2.x, ac0); ac0 = fmaf(hv.w, w3.x, ac0);
        ac1 = fmaf(hv.x, w0.y, ac1); ac1 = fmaf(hv.y, w1.y, ac1);
        ac1 = fmaf(hv.z, w2.y, ac1); ac1 = fmaf(hv.w, w3.y, ac1);
        ac2 = fmaf(hv.x, w0.z, ac2); ac2 = fmaf(hv.y, w1.z, ac2);
        ac2 = fmaf(hv.z, w2.z, ac2); ac2 = fmaf(hv.w, w3.z, ac2);
        ac3 = fmaf(hv.x, w0.w, ac3); ac3 = fmaf(hv.y, w1.w, ac3);
        ac3 = fmaf(hv.z, w2.w, ac3); ac3 = fmaf(hv.w, w3.w, ac3);
    }
    float d = g_dinv[node];
    float4 o = make_float4(ac0 * d, ac1 * d, ac2 * d, ac3 * d);
    *(float4*)&dst[(size_t)node * HD + part * 4] = o;
}

// ---------------- final agg (layer 3): gather g_t -> g_h ----------------
__global__ void __launch_bounds__(256, 6) k_agg(const float* __restrict__ b) {
    int tid  = threadIdx.x;
    int node = blockIdx.x * 16 + (tid >> 4);
    int part = tid & 15;
    float4 o = gather_h((const float4*)g_t, node, part, b);
    ((float4*)g_h)[(size_t)node * 16 + part] = o;
}

// ---------------- MLP head + p output + weighted-BCE ----------------
__global__ void k_head(const float* __restrict__ lW1, const float* __restrict__ lb1,
                       const float* __restrict__ lW2, const float* __restrict__ lb2,
                       const int* __restrict__ labels, float* __restrict__ out_p) {
    __shared__ float sW1[HD * 8];
    __shared__ float sb1[8];
    __shared__ float sW2[8];
    __shared__ float swsum[8];
    int tid = threadIdx.x;
    for (int j = tid; j < HD * 8; j += 256) sW1[j] = lW1[j];
    if (tid < 8) { sb1[tid] = lb1[tid]; sW2[tid] = lW2[tid]; }
    __syncthreads();

    int i = blockIdx.x * 256 + tid;
    float term = 0.f;
    if (i < NN) {
        float z[8];
        #pragma unroll
        for (int o = 0; o < 8; o++) z[o] = sb1[o];
        const float* hr = &g_h[(size_t)i * HD];
        #pragma unroll
        for (int j4 = 0; j4 < HD; j4 += 4) {
            float4 hv = *(const float4*)&hr[j4];
            #pragma unroll
            for (int o = 0; o < 8; o++) {
                z[o] = fmaf(hv.x, sW1[(j4 + 0) * 8 + o], z[o]);
                z[o] = fmaf(hv.y, sW1[(j4 + 1) * 8 + o], z[o]);
                z[o] = fmaf(hv.z, sW1[(j4 + 2) * 8 + o], z[o]);
                z[o] = fmaf(hv.w, sW1[(j4 + 3) * 8 + o], z[o]);
            }
        }
        float z2 = lb2[0];
        #pragma unroll
        for (int o = 0; o < 8; o++) z2 += fmaxf(z[o], 0.f) * sW2[o];
        float p = 1.f / (1.f + expf(-z2));
        out_p[i] = p;

        float pm = (float)g_lsum * (1.0f / NN);
        float y = (float)labels[i];
        float w = y * (1.f - pm) + (1.f - y) * pm;
        float pc = fminf(fmaxf(p, 1e-7f), 1.f - 1e-7f);
        float bce = -(y * logf(pc) + (1.f - y) * logf(1.f - pc));
        term = w * bce;
    }
    #pragma unroll
    for (int off = 16; off; off >>= 1) term += __shfl_down_sync(0xffffffffu, term, off);
    if ((tid & 31) == 0) swsum[tid >> 5] = term;
    __syncthreads();
    if (tid == 0) {
        float s = 0.f;
        #pragma unroll
        for (int k2 = 0; k2 < 8; k2++) s += swsum[k2];
        atomicAdd(&g_loss, s);
    }
}

__global__ void k_final(float* __restrict__ out) {
    out[0] = g_loss * (1.0f / NN);
}

// ---------------- launch ----------------
extern "C" void kernel_launch(void* const* d_in, const int* in_sizes, int n_in,
                              void* d_out, int out_size) {
    const float* x      = (const float*)d_in[0];
    const int*   ei     = (const int*)d_in[1];
    const int*   labels = (const int*)d_in[2];
    const float* W1  = (const float*)d_in[3];
    const float* b1  = (const float*)d_in[4];
    const float* W2  = (const float*)d_in[5];
    const float* b2  = (const float*)d_in[6];
    const float* W3  = (const float*)d_in[7];
    const float* b3  = (const float*)d_in[8];
    const float* lW1 = (const float*)d_in[9];
    const float* lb1 = (const float*)d_in[10];
    const float* lW2 = (const float*)d_in[11];
    const float* lb2 = (const float*)d_in[12];

    float* out = (float*)d_out;
    int loss_elems = out_size - NN;
    float* out_p = out + (loss_elems > 0 ? loss_elems : 0);

    const int TPB = 256;
    const int agg_blocks = NN / 16;   // 6250

    k_ic   <<<NB_N + NB_E, TPB>>>(labels, ei);                    // 1
    k_scan <<<1, 1024>>>();                                       // 2
    k_gemmfill<<<GEMM1_BLOCKS + NB_E, TPB>>>(x, W1, ei);          // 3  t1 -> A
    k_agg_gemm<true><<<agg_blocks, TPB>>>(b1, W2);                // 4  A->B  <- profiled
    k_agg_gemm<false><<<agg_blocks, TPB>>>(b2, W3);               // 5  B->A
    k_agg<<<agg_blocks, TPB>>>(b3);                               // 6  A->g_h
    k_head<<<NB_N, TPB>>>(lW1, lb1, lW2, lb2, labels, out_p);     // 7
    if (loss_elems > 0) k_final<<<1, 1>>>(out);                   // 8
}

// round 16
// speedup vs baseline: 1.0983x; 1.0983x over previous
#include <cuda_runtime.h>
#include <cstdint>

#define NN 100000
#define NE 1600000
#define NF 128
#define HD 64

#define NB_N ((NN + 255) / 256)   // 391
#define NB_E ((NE + 255) / 256)   // 6250
#define GEMM1_BLOCKS 592

// ---------------- scratch (no allocs allowed) ----------------
__device__ __align__(16) float g_dinv[NN];
__device__ __align__(16) float g_t [NN * HD];    // (h @ W) * dinv[row]
__device__ __align__(16) float g_h [NN * HD];    // layer output (layers 1,2)
__device__ __align__(16) int g_deg[NN];
__device__ __align__(16) int g_cursor[NN];
__device__ __align__(16) int g_rowstart[NN + 1];
__device__ __align__(16) int g_csr[NE];
__device__ float g_loss;
__device__ int   g_lsum;

// ---------------- 1: fused init (nodes) + count (edges) ----------------
__global__ void k_ic(const int* __restrict__ labels, const int* __restrict__ ei) {
    int bid = blockIdx.x;
    if (bid < NB_N) {
        int i = bid * 256 + threadIdx.x;
        if (i == 0) { g_loss = 0.f; g_lsum = 0; }
        int v = 0;
        if (i < NN) { g_deg[i] = 0; v = labels[i]; }
        #pragma unroll
        for (int off = 16; off; off >>= 1) v += __shfl_down_sync(0xffffffffu, v, off);
        if ((threadIdx.x & 31) == 0 && v) atomicAdd(&g_lsum, v);
    } else {
        int e = (bid - NB_N) * 256 + threadIdx.x;
        if (e < NE) {
            unsigned c = (unsigned)ei[NE + e];
            if (c < NN) atomicAdd(&g_deg[c], 1);
        }
    }
}

// ---------------- 2: 1-block scan -> rowstart, cursor, dinv ----------------
__global__ void k_scan() {
    const int T = 1024;
    const int CH = (NN + T - 1) / T;
    __shared__ int sh[T];
    int tid = threadIdx.x;
    int lo = tid * CH, hi = lo + CH; if (hi > NN) hi = NN;
    int s = 0;
    for (int i = lo; i < hi; i++) s += g_deg[i];
    sh[tid] = s;
    __syncthreads();
    for (int off = 1; off < T; off <<= 1) {
        int v = (tid >= off) ? sh[tid - off] : 0;
        __syncthreads();
        sh[tid] += v;
        __syncthreads();
    }
    int run = sh[tid] - s;
    for (int i = lo; i < hi; i++) {
        int d = g_deg[i];
        g_rowstart[i] = run;
        g_cursor[i]   = run;
        g_dinv[i]     = rsqrtf((float)(d + 1));
        run += d;
    }
    if (tid == T - 1) g_rowstart[NN] = run;
}

// ---------------- gemm body (R10-proven retile) ----------------
template <int K, bool USEG>
__device__ __forceinline__ void gemm_body(const float* __restrict__ hin,
                                          const float* __restrict__ W,
                                          float* sW, float4 (*srow)[K / 4],
                                          int bid, int nblocks) {
    const float* src = USEG ? g_h : hin;
    int tid = threadIdx.x;
    for (int j = tid; j < K * HD / 4; j += 256)
        ((float4*)sW)[j] = ((const float4*)W)[j];

    int c2 = tid & 31;
    int rt = tid >> 5;

    for (int rb = bid * 32; rb < NN; rb += nblocks * 32) {
        __syncthreads();
        for (int j = tid; j < 32 * (K / 4); j += 256) {
            int r = j / (K / 4), kk = j % (K / 4);
            srow[r][kk] = ((const float4*)(src + (size_t)(rb + r) * K))[kk];
        }
        __syncthreads();

        float acc0[4], acc1[4];
        #pragma unroll
        for (int rr = 0; rr < 4; rr++) { acc0[rr] = 0.f; acc1[rr] = 0.f; }

        #pragma unroll
        for (int k4 = 0; k4 < K / 4; k4++) {
            float2 wa = *(const float2*)&sW[(4 * k4 + 0) * HD + 2 * c2];
            float2 wb = *(const float2*)&sW[(4 * k4 + 1) * HD + 2 * c2];
            float2 wc = *(const float2*)&sW[(4 * k4 + 2) * HD + 2 * c2];
            float2 wd = *(const float2*)&sW[(4 * k4 + 3) * HD + 2 * c2];
            #pragma unroll
            for (int rr = 0; rr < 4; rr++) {
                float4 h = srow[rt * 4 + rr][k4];
                acc0[rr] = fmaf(h.x, wa.x, acc0[rr]);
                acc0[rr] = fmaf(h.y, wb.x, acc0[rr]);
                acc0[rr] = fmaf(h.z, wc.x, acc0[rr]);
                acc0[rr] = fmaf(h.w, wd.x, acc0[rr]);
                acc1[rr] = fmaf(h.x, wa.y, acc1[rr]);
                acc1[rr] = fmaf(h.y, wb.y, acc1[rr]);
                acc1[rr] = fmaf(h.z, wc.y, acc1[rr]);
                acc1[rr] = fmaf(h.w, wd.y, acc1[rr]);
            }
        }
        #pragma unroll
        for (int rr = 0; rr < 4; rr++) {
            int gr = rb + rt * 4 + rr;
            float d = g_dinv[gr];
            float2 o = make_float2(acc0[rr] * d, acc1[rr] * d);
            *(float2*)&g_t[(size_t)gr * HD + 2 * c2] = o;
        }
    }
}

// ---------------- 3: fused [gemm1 || fill] ----------------
__global__ void __launch_bounds__(256) k_gemmfill(const float* __restrict__ x,
                                                  const float* __restrict__ W1,
                                                  const int* __restrict__ ei) {
    __shared__ __align__(16) float  sW[NF * HD];        // 32KB
    __shared__ __align__(16) float4 srow[32][NF / 4];   // 16KB
    int bid = blockIdx.x;
    if (bid >= GEMM1_BLOCKS) {
        int e = (bid - GEMM1_BLOCKS) * 256 + threadIdx.x;
        if (e < NE) {
            unsigned src = (unsigned)ei[e];
            unsigned dst = (unsigned)ei[NE + e];
            if (src < NN && dst < NN) {
                int pos = atomicAdd(&g_cursor[dst], 1);
                g_csr[pos] = (int)src;
            }
        }
        return;
    }
    gemm_body<NF, false>(x, W1, sW, srow, bid, GEMM1_BLOCKS);
}

// ---------------- gemm2/3 standalone ----------------
template <int K, bool USEG>
__global__ void __launch_bounds__(256) k_gemm(const float* __restrict__ hin,
                                              const float* __restrict__ W) {
    __shared__ __align__(16) float  sW[K * HD];
    __shared__ __align__(16) float4 srow[32][K / 4];
    gemm_body<K, USEG>(hin, W, sW, srow, blockIdx.x, gridDim.x);
}

// ---------------- gather core (R14-proven: unroll-4, two chains) ----------
__device__ __forceinline__ float4 gather_h(int node, int part,
                                           const float* __restrict__ b) {
    const float4* __restrict__ t4 = (const float4*)g_t;
    int s = g_rowstart[node];
    int e = g_rowstart[node + 1];

    float4 a0 = t4[(size_t)node * 16 + part];   // self loop
    float4 a1 = make_float4(0.f, 0.f, 0.f, 0.f);
    int i = s;
    for (; i + 4 <= e; i += 4) {
        int s0 = g_csr[i],     s1 = g_csr[i + 1];
        int s2 = g_csr[i + 2], s3 = g_csr[i + 3];
        float4 v0 = t4[(size_t)s0 * 16 + part];
        float4 v1 = t4[(size_t)s1 * 16 + part];
        float4 v2 = t4[(size_t)s2 * 16 + part];
        float4 v3 = t4[(size_t)s3 * 16 + part];
        a0.x += v0.x; a0.y += v0.y; a0.z += v0.z; a0.w += v0.w;
        a1.x += v1.x; a1.y += v1.y; a1.z += v1.z; a1.w += v1.w;
        a0.x += v2.x; a0.y += v2.y; a0.z += v2.z; a0.w += v2.w;
        a1.x += v3.x; a1.y += v3.y; a1.z += v3.z; a1.w += v3.w;
    }
    for (; i < e; i++) {
        float4 v = t4[(size_t)g_csr[i] * 16 + part];
        a0.x += v.x; a0.y += v.y; a0.z += v.z; a0.w += v.w;
    }
    float4 acc = make_float4(a0.x + a1.x, a0.y + a1.y, a0.z + a1.z, a0.w + a1.w);

    float d = g_dinv[node];
    float4 bb = *(const float4*)&b[part * 4];
    float4 o;
    o.x = fmaxf(fmaf(d, acc.x, bb.x), 0.f);
    o.y = fmaxf(fmaf(d, acc.y, bb.y), 0.f);
    o.z = fmaxf(fmaf(d, acc.z, bb.z), 0.f);
    o.w = fmaxf(fmaf(d, acc.w, bb.w), 0.f);
    return o;
}

// ---------------- agg (layers 1,2): gather -> g_h ----------------
__global__ void __launch_bounds__(256, 6) k_agg(const float* __restrict__ b) {
    int tid  = threadIdx.x;
    int node = blockIdx.x * 16 + (tid >> 4);
    int part = tid & 15;
    float4 o = gather_h(node, part, b);
    ((float4*)g_h)[(size_t)node * 16 + part] = o;
}

// ---------------- agg3 fused with head (bit-identical head math) ----------
__global__ void __launch_bounds__(256) k_agg_head(const float* __restrict__ b,
                                                  const float* __restrict__ lW1,
                                                  const float* __restrict__ lb1,
                                                  const float* __restrict__ lW2,
                                                  const float* __restrict__ lb2,
                                                  const int* __restrict__ labels,
                                                  float* __restrict__ out_p) {
    __shared__ float sW1[HD * 8];
    __shared__ __align__(16) float shh[16][HD + 8];   // padded rows (16B-aligned)
    __shared__ float sterm[16];
    int tid  = threadIdx.x;
    int nl   = tid >> 4;
    int part = tid & 15;
    int node = blockIdx.x * 16 + nl;   // NN % 16 == 0

    for (int j = tid; j < HD * 8; j += 256) sW1[j] = lW1[j];

    float4 h = gather_h(node, part, b);
    *(float4*)&shh[nl][part * 4] = h;
    __syncthreads();

    // threads 0..15: one node each, EXACT k_head serial math from smem
    if (tid < 16) {
        int n = blockIdx.x * 16 + tid;
        float z[8];
        #pragma unroll
        for (int o = 0; o < 8; o++) z[o] = lb1[o];
        const float* hr = shh[tid];
        #pragma unroll
        for (int j4 = 0; j4 < HD; j4 += 4) {
            float4 hv = *(const float4*)&hr[j4];
            #pragma unroll
            for (int o = 0; o < 8; o++) {
                z[o] = fmaf(hv.x, sW1[(j4 + 0) * 8 + o], z[o]);
                z[o] = fmaf(hv.y, sW1[(j4 + 1) * 8 + o], z[o]);
                z[o] = fmaf(hv.z, sW1[(j4 + 2) * 8 + o], z[o]);
                z[o] = fmaf(hv.w, sW1[(j4 + 3) * 8 + o], z[o]);
            }
        }
        float z2 = lb2[0];
        #pragma unroll
        for (int o = 0; o < 8; o++) z2 += fmaxf(z[o], 0.f) * lW2[o];
        float p = 1.f / (1.f + expf(-z2));
        out_p[n] = p;

        float pm = (float)g_lsum * (1.0f / NN);
        float y = (float)labels[n];
        float w = y * (1.f - pm) + (1.f - y) * pm;
        float pc = fminf(fmaxf(p, 1e-7f), 1.f - 1e-7f);
        float bce = -(y * logf(pc) + (1.f - y) * logf(1.f - pc));
        sterm[tid] = w * bce;
    }
    __syncthreads();
    if (tid == 0) {
        float s = 0.f;
        #pragma unroll
        for (int k2 = 0; k2 < 16; k2++) s += sterm[k2];
        atomicAdd(&g_loss, s);
    }
}

__global__ void k_final(float* __restrict__ out) {
    out[0] = g_loss * (1.0f / NN);
}

// ---------------- launch ----------------
extern "C" void kernel_launch(void* const* d_in, const int* in_sizes, int n_in,
                              void* d_out, int out_size) {
    const float* x      = (const float*)d_in[0];
    const int*   ei     = (const int*)d_in[1];
    const int*   labels = (const int*)d_in[2];
    const float* W1  = (const float*)d_in[3];
    const float* b1  = (const float*)d_in[4];
    const float* W2  = (const float*)d_in[5];
    const float* b2  = (const float*)d_in[6];
    const float* W3  = (const float*)d_in[7];
    const float* b3  = (const float*)d_in[8];
    const float* lW1 = (const float*)d_in[9];
    const float* lb1 = (const float*)d_in[10];
    const float* lW2 = (const float*)d_in[11];
    const float* lb2 = (const float*)d_in[12];

    float* out = (float*)d_out;
    int loss_elems = out_size - NN;
    float* out_p = out + (loss_elems > 0 ? loss_elems : 0);

    const int TPB = 256;
    const int agg_blocks   = NN / 16;   // 6250
    const int gemm2_blocks = NN / 32;   // 3125

    k_ic   <<<NB_N + NB_E, TPB>>>(labels, ei);                    // 1
    k_scan <<<1, 1024>>>();                                       // 2
    k_gemmfill<<<GEMM1_BLOCKS + NB_E, TPB>>>(x, W1, ei);          // 3
    k_agg<<<agg_blocks, TPB>>>(b1);                               // 4  <- profiled
    k_gemm<HD, true><<<gemm2_blocks, TPB>>>(nullptr, W2);         // 5
    k_agg<<<agg_blocks, TPB>>>(b2);                               // 6
    k_gemm<HD, true><<<gemm2_blocks, TPB>>>(nullptr, W3);         // 7
    k_agg_head<<<agg_blocks, TPB>>>(b3, lW1, lb1, lW2, lb2, labels, out_p);  // 8
    if (loss_elems > 0) k_final<<<1, 1>>>(out);                   // 9
}

// round 17
// speedup vs baseline: 1.1049x; 1.0060x over previous
#include <cuda_runtime.h>
#include <cstdint>

#define NN 100000
#define NE 1600000
#define NF 128
#define HD 64

#define NB_N ((NN + 255) / 256)   // 391
#define NB_E ((NE + 255) / 256)   // 6250
#define GEMM1_BLOCKS 592

// ---------------- scratch (no allocs allowed) ----------------
__device__ __align__(16) float g_dinv[NN];
__device__ __align__(16) float g_t [NN * HD];    // (h @ W) * dinv[row]
__device__ __align__(16) float g_h [NN * HD];    // layer output (layers 1,2)
__device__ __align__(16) int g_deg[NN];
__device__ __align__(16) int g_cursor[NN];
__device__ __align__(16) int g_rowstart[NN + 1];
__device__ __align__(16) int g_csr[NE];
__device__ float g_loss;
__device__ int   g_lsum;

// ---------------- 1: fused init (nodes) + count (edges) ----------------
__global__ void k_ic(const int* __restrict__ labels, const int* __restrict__ ei) {
    int bid = blockIdx.x;
    if (bid < NB_N) {
        int i = bid * 256 + threadIdx.x;
        if (i == 0) { g_loss = 0.f; g_lsum = 0; }
        int v = 0;
        if (i < NN) { g_deg[i] = 0; v = labels[i]; }
        #pragma unroll
        for (int off = 16; off; off >>= 1) v += __shfl_down_sync(0xffffffffu, v, off);
        if ((threadIdx.x & 31) == 0 && v) atomicAdd(&g_lsum, v);
    } else {
        int e = (bid - NB_N) * 256 + threadIdx.x;
        if (e < NE) {
            unsigned c = (unsigned)ei[NE + e];
            if (c < NN) atomicAdd(&g_deg[c], 1);
        }
    }
}

// ---------------- 2: 1-block scan -> rowstart, cursor, dinv ----------------
__global__ void k_scan() {
    const int T = 1024;
    const int CH = (NN + T - 1) / T;
    __shared__ int sh[T];
    int tid = threadIdx.x;
    int lo = tid * CH, hi = lo + CH; if (hi > NN) hi = NN;
    int s = 0;
    for (int i = lo; i < hi; i++) s += g_deg[i];
    sh[tid] = s;
    __syncthreads();
    for (int off = 1; off < T; off <<= 1) {
        int v = (tid >= off) ? sh[tid - off] : 0;
        __syncthreads();
        sh[tid] += v;
        __syncthreads();
    }
    int run = sh[tid] - s;
    for (int i = lo; i < hi; i++) {
        int d = g_deg[i];
        g_rowstart[i] = run;
        g_cursor[i]   = run;
        g_dinv[i]     = rsqrtf((float)(d + 1));
        run += d;
    }
    if (tid == T - 1) g_rowstart[NN] = run;
}

// ---------------- compute core (R10-proven retile; bit-exact chains) -------
template <int K>
__device__ __forceinline__ void gemm_compute(const float* sW,
                                             const float4 (*srow)[K / 4],
                                             int rb, int c2, int rt) {
    float acc0[4], acc1[4];
    #pragma unroll
    for (int rr = 0; rr < 4; rr++) { acc0[rr] = 0.f; acc1[rr] = 0.f; }

    #pragma unroll
    for (int k4 = 0; k4 < K / 4; k4++) {
        float2 wa = *(const float2*)&sW[(4 * k4 + 0) * HD + 2 * c2];
        float2 wb = *(const float2*)&sW[(4 * k4 + 1) * HD + 2 * c2];
        float2 wc = *(const float2*)&sW[(4 * k4 + 2) * HD + 2 * c2];
        float2 wd = *(const float2*)&sW[(4 * k4 + 3) * HD + 2 * c2];
        #pragma unroll
        for (int rr = 0; rr < 4; rr++) {
            float4 h = srow[rt * 4 + rr][k4];
            acc0[rr] = fmaf(h.x, wa.x, acc0[rr]);
            acc0[rr] = fmaf(h.y, wb.x, acc0[rr]);
            acc0[rr] = fmaf(h.z, wc.x, acc0[rr]);
            acc0[rr] = fmaf(h.w, wd.x, acc0[rr]);
            acc1[rr] = fmaf(h.x, wa.y, acc1[rr]);
            acc1[rr] = fmaf(h.y, wb.y, acc1[rr]);
            acc1[rr] = fmaf(h.z, wc.y, acc1[rr]);
            acc1[rr] = fmaf(h.w, wd.y, acc1[rr]);
        }
    }
    #pragma unroll
    for (int rr = 0; rr < 4; rr++) {
        int gr = rb + rt * 4 + rr;
        float d = g_dinv[gr];
        float2 o = make_float2(acc0[rr] * d, acc1[rr] * d);
        *(float2*)&g_t[(size_t)gr * HD + 2 * c2] = o;
    }
}

// ---------------- gemm1 body (synchronous, proven) ----------------
__device__ __forceinline__ void gemm1_body(const float* __restrict__ hin,
                                           const float* __restrict__ W,
                                           float* sW, float4 (*srow)[NF / 4],
                                           int bid, int nblocks) {
    int tid = threadIdx.x;
    for (int j = tid; j < NF * HD / 4; j += 256)
        ((float4*)sW)[j] = ((const float4*)W)[j];
    int c2 = tid & 31;
    int rt = tid >> 5;
    for (int rb = bid * 32; rb < NN; rb += nblocks * 32) {
        __syncthreads();
        for (int j = tid; j < 32 * (NF / 4); j += 256) {
            int r = j / (NF / 4), kk = j % (NF / 4);
            srow[r][kk] = ((const float4*)(hin + (size_t)(rb + r) * NF))[kk];
        }
        __syncthreads();
        gemm_compute<NF>(sW, srow, rb, c2, rt);
    }
}

// ---------------- 3: fused [gemm1 || fill] ----------------
__global__ void __launch_bounds__(256) k_gemmfill(const float* __restrict__ x,
                                                  const float* __restrict__ W1,
                                                  const int* __restrict__ ei) {
    __shared__ __align__(16) float  sW[NF * HD];        // 32KB
    __shared__ __align__(16) float4 srow[32][NF / 4];   // 16KB
    int bid = blockIdx.x;
    if (bid >= GEMM1_BLOCKS) {
        int e = (bid - GEMM1_BLOCKS) * 256 + threadIdx.x;
        if (e < NE) {
            unsigned src = (unsigned)ei[e];
            unsigned dst = (unsigned)ei[NE + e];
            if (src < NN && dst < NN) {
                int pos = atomicAdd(&g_cursor[dst], 1);
                g_csr[pos] = (int)src;
            }
        }
        return;
    }
    gemm1_body(x, W1, sW, srow, bid, GEMM1_BLOCKS);
}

// ---------------- cp.async helpers ----------------
__device__ __forceinline__ void cp16(void* smem_dst, const void* gmem_src) {
    uint32_t sa = (uint32_t)__cvta_generic_to_shared(smem_dst);
    asm volatile("cp.async.cg.shared.global [%0], [%1], 16;"
                 :: "r"(sa), "l"(gmem_src));
}
#define CP_COMMIT() asm volatile("cp.async.commit_group;" ::: "memory")
#define CP_WAIT1()  asm volatile("cp.async.wait_group 1;" ::: "memory")

template <int K>
__device__ __forceinline__ void stage_tile(float4 (*buf)[K / 4],
                                           const float* __restrict__ src, int rb) {
    int tid = threadIdx.x;
    #pragma unroll
    for (int j = tid; j < 32 * (K / 4); j += 256) {
        int r = j / (K / 4), kk = j % (K / 4);
        cp16(&buf[r][kk], ((const float4*)(src + (size_t)(rb + r) * K)) + kk);
    }
}

// ---------------- gemm2/3: cp.async double-buffered pipeline ----------------
template <int K>
__global__ void __launch_bounds__(256) k_gemm_pipe(const float* __restrict__ W) {
    __shared__ __align__(16) float  sW[K * HD];          // 16KB (K=64)
    __shared__ __align__(16) float4 srow[2][32][K / 4];  // 2x8KB
    const float* src = g_h;
    int tid = threadIdx.x;
    for (int j = tid; j < K * HD / 4; j += 256)
        ((float4*)sW)[j] = ((const float4*)W)[j];

    int c2 = tid & 31;
    int rt = tid >> 5;
    int stride = gridDim.x * 32;
    int rb0 = blockIdx.x * 32;

    if (rb0 < NN) stage_tile<K>(srow[0], src, rb0);
    CP_COMMIT();

    int buf = 0;
    for (int rb = rb0; rb < NN; rb += stride) {
        int rbn = rb + stride;
        if (rbn < NN) stage_tile<K>(srow[buf ^ 1], src, rbn);
        CP_COMMIT();
        CP_WAIT1();
        __syncthreads();
        gemm_compute<K>(sW, srow[buf], rb, c2, rt);
        __syncthreads();
        buf ^= 1;
    }
}

// ---------------- gather core (R14-proven: unroll-4, two chains) ----------
__device__ __forceinline__ float4 gather_h(int node, int part,
                                           const float* __restrict__ b) {
    const float4* __restrict__ t4 = (const float4*)g_t;
    int s = g_rowstart[node];
    int e = g_rowstart[node + 1];

    float4 a0 = t4[(size_t)node * 16 + part];   // self loop
    float4 a1 = make_float4(0.f, 0.f, 0.f, 0.f);
    int i = s;
    for (; i + 4 <= e; i += 4) {
        int s0 = g_csr[i],     s1 = g_csr[i + 1];
        int s2 = g_csr[i + 2], s3 = g_csr[i + 3];
        float4 v0 = t4[(size_t)s0 * 16 + part];
        float4 v1 = t4[(size_t)s1 * 16 + part];
        float4 v2 = t4[(size_t)s2 * 16 + part];
        float4 v3 = t4[(size_t)s3 * 16 + part];
        a0.x += v0.x; a0.y += v0.y; a0.z += v0.z; a0.w += v0.w;
        a1.x += v1.x; a1.y += v1.y; a1.z += v1.z; a1.w += v1.w;
        a0.x += v2.x; a0.y += v2.y; a0.z += v2.z; a0.w += v2.w;
        a1.x += v3.x; a1.y += v3.y; a1.z += v3.z; a1.w += v3.w;
    }
    for (; i < e; i++) {
        float4 v = t4[(size_t)g_csr[i] * 16 + part];
        a0.x += v.x; a0.y += v.y; a0.z += v.z; a0.w += v.w;
    }
    float4 acc = make_float4(a0.x + a1.x, a0.y + a1.y, a0.z + a1.z, a0.w + a1.w);

    float d = g_dinv[node];
    float4 bb = *(const float4*)&b[part * 4];
    float4 o;
    o.x = fmaxf(fmaf(d, acc.x, bb.x), 0.f);
    o.y = fmaxf(fmaf(d, acc.y, bb.y), 0.f);
    o.z = fmaxf(fmaf(d, acc.z, bb.z), 0.f);
    o.w = fmaxf(fmaf(d, acc.w, bb.w), 0.f);
    return o;
}

// ---------------- agg (layers 1,2): gather -> g_h ----------------
__global__ void __launch_bounds__(256, 6) k_agg(const float* __restrict__ b) {
    int tid  = threadIdx.x;
    int node = blockIdx.x * 16 + (tid >> 4);
    int part = tid & 15;
    float4 o = gather_h(node, part, b);
    ((float4*)g_h)[(size_t)node * 16 + part] = o;
}

// ---------------- agg3 fused with head (bit-identical head math) ----------
__global__ void __launch_bounds__(256) k_agg_head(const float* __restrict__ b,
                                                  const float* __restrict__ lW1,
                                                  const float* __restrict__ lb1,
                                                  const float* __restrict__ lW2,
                                                  const float* __restrict__ lb2,
                                                  const int* __restrict__ labels,
                                                  float* __restrict__ out_p) {
    __shared__ float sW1[HD * 8];
    __shared__ __align__(16) float shh[16][HD + 8];
    __shared__ float sterm[16];
    int tid  = threadIdx.x;
    int nl   = tid >> 4;
    int part = tid & 15;
    int node = blockIdx.x * 16 + nl;

    for (int j = tid; j < HD * 8; j += 256) sW1[j] = lW1[j];

    float4 h = gather_h(node, part, b);
    *(float4*)&shh[nl][part * 4] = h;
    __syncthreads();

    if (tid < 16) {
        int n = blockIdx.x * 16 + tid;
        float z[8];
        #pragma unroll
        for (int o = 0; o < 8; o++) z[o] = lb1[o];
        const float* hr = shh[tid];
        #pragma unroll
        for (int j4 = 0; j4 < HD; j4 += 4) {
            float4 hv = *(const float4*)&hr[j4];
            #pragma unroll
            for (int o = 0; o < 8; o++) {
                z[o] = fmaf(hv.x, sW1[(j4 + 0) * 8 + o], z[o]);
                z[o] = fmaf(hv.y, sW1[(j4 + 1) * 8 + o], z[o]);
                z[o] = fmaf(hv.z, sW1[(j4 + 2) * 8 + o], z[o]);
                z[o] = fmaf(hv.w, sW1[(j4 + 3) * 8 + o], z[o]);
            }
        }
        float z2 = lb2[0];
        #pragma unroll
        for (int o = 0; o < 8; o++) z2 += fmaxf(z[o], 0.f) * lW2[o];
        float p = 1.f / (1.f + expf(-z2));
        out_p[n] = p;

        float pm = (float)g_lsum * (1.0f / NN);
        float y = (float)labels[n];
        float w = y * (1.f - pm) + (1.f - y) * pm;
        float pc = fminf(fmaxf(p, 1e-7f), 1.f - 1e-7f);
        float bce = -(y * logf(pc) + (1.f - y) * logf(1.f - pc));
        sterm[tid] = w * bce;
    }
    __syncthreads();
    if (tid == 0) {
        float s = 0.f;
        #pragma unroll
        for (int k2 = 0; k2 < 16; k2++) s += sterm[k2];
        atomicAdd(&g_loss, s);
    }
}

__global__ void k_final(float* __restrict__ out) {
    out[0] = g_loss * (1.0f / NN);
}

// ---------------- launch ----------------
extern "C" void kernel_launch(void* const* d_in, const int* in_sizes, int n_in,
                              void* d_out, int out_size) {
    const float* x      = (const float*)d_in[0];
    const int*   ei     = (const int*)d_in[1];
    const int*   labels = (const int*)d_in[2];
    const float* W1  = (const float*)d_in[3];
    const float* b1  = (const float*)d_in[4];
    const float* W2  = (const float*)d_in[5];
    const float* b2  = (const float*)d_in[6];
    const float* W3  = (const float*)d_in[7];
    const float* b3  = (const float*)d_in[8];
    const float* lW1 = (const float*)d_in[9];
    const float* lb1 = (const float*)d_in[10];
    const float* lW2 = (const float*)d_in[11];
    const float* lb2 = (const float*)d_in[12];

    float* out = (float*)d_out;
    int loss_elems = out_size - NN;
    float* out_p = out + (loss_elems > 0 ? loss_elems : 0);

    const int TPB = 256;
    const int agg_blocks = NN / 16;   // 6250

    k_ic   <<<NB_N + NB_E, TPB>>>(labels, ei);                    // 1
    k_scan <<<1, 1024>>>();                                       // 2
    k_gemmfill<<<GEMM1_BLOCKS + NB_E, TPB>>>(x, W1, ei);          // 3
    k_agg<<<agg_blocks, TPB>>>(b1);                               // 4  <- profiled
    k_gemm_pipe<HD><<<592, TPB>>>(W2);                            // 5
    k_agg<<<agg_blocks, TPB>>>(b2);                               // 6
    k_gemm_pipe<HD><<<592, TPB>>>(W3);                            // 7
    k_agg_head<<<agg_blocks, TPB>>>(b3, lW1, lb1, lW2, lb2, labels, out_p);  // 8
    if (loss_elems > 0) k_final<<<1, 1>>>(out);                   // 9
}